// round 9
// baseline (speedup 1.0000x reference)
#include <cuda_runtime.h>
#include <math.h>

#define NN 50000
#define NE 400000
#define NG 64
#define DIN 200
#define DH 32
#define NBLK 196    // ceil(NN/256)
#define EBLK2 782   // ceil(NE/512)  (edge kernels: 256 thr x 2 edges)
#define GBLK 391    // ceil(NN/128)  (GEMM blocks: 256 thr, 128 nodes, 64 cols)

// ---------------- scratch (device globals — no allocation allowed) ----------
// NOTE: never pass these as kernel args from host code (host shadow symbol +
// ATS silently reads zeros). Select ping-pong buffers with an int in device code.
__device__ __align__(16) float g_tr_a[NN * DH];
__device__ __align__(16) float g_tr_b[NN * DH];
__device__ __align__(16) float g_root_a[NN * DH];
__device__ __align__(16) float g_root_b[NN * DH];
__device__ float g_sums[NG * DH];

__device__ int g_flag_ei;    // nonzero -> edge_index is int32
__device__ int g_flag_b;     // nonzero -> batch is int32

__device__ int g_cnt[NN];
__device__ int g_off[NN];
__device__ int g_cur[NN];
__device__ int g_total;
__device__ int g_esrc[NE];
__device__ int g_gstart[NG + 1];

__device__ __forceinline__ float elu1(float v) { return v > 0.f ? v : expm1f(v); }

#define FMA_X2(acc, a, b) \
    asm("fma.rn.f32x2 %0, %1, %2, %0;" : "+l"(acc) : "l"(a), "l"(b))
#define DUP_X2(out, x) \
    asm("mov.b64 %0, {%1, %1};" : "=l"(out) : "r"(__float_as_uint(x)))
#define UNPK_X2(lo, hi, in) \
    asm("mov.b64 {%0, %1}, %2;" : "=f"(lo), "=f"(hi) : "l"(in))
#define PACK_X2(out, lo, hi) \
    asm("mov.b64 %0, {%1, %2};" : "=l"(out) : "f"(lo), "f"(hi))

// ---------------------------------------------------------------------------
// decode helpers (dtype-aware, clamped)
// ---------------------------------------------------------------------------
__device__ __forceinline__ int edge_at(const void* ei_raw, int idx, int is32)
{
    int v = is32 ? ((const int*)ei_raw)[idx] : (int)((const long long*)ei_raw)[idx];
    v &= 0x7fffffff;
    return (v < NN) ? v : 0;
}

__device__ __forceinline__ int batch_at(const void* b_raw, int i, int is32)
{
    int g = is32 ? ((const int*)b_raw)[i] : (int)((const long long*)b_raw)[i];
    g &= 0x7fffffff;
    return (g < NG) ? g : (NG - 1);
}

// ---------------------------------------------------------------------------
// Kernel 1: zero scratch + dtype detection (sample odd 32-bit words: int64
// values < 2^31 have zero high words; int32 payloads essentially never do)
// ---------------------------------------------------------------------------
__global__ void k_detect_zero(const unsigned* __restrict__ ei_w,
                              const unsigned* __restrict__ b_w)
{
    const int i = blockIdx.x * blockDim.x + threadIdx.x;
    if (i < NN) g_cnt[i] = 0;
    if (i < NG * DH) g_sums[i] = 0.f;
    if (i == 0) g_total = 0;

    if (blockIdx.x == 0) {
        __shared__ int s_ei, s_b;
        const int tid = threadIdx.x;
        if (tid == 0) { s_ei = 0; s_b = 0; }
        __syncthreads();
        { const int k = tid * 1562;  if (ei_w[2 * k + 1] != 0) atomicOr(&s_ei, 1); }
        { const int k = 24744 + tid; if (b_w[2 * k + 1] != 0)  atomicOr(&s_b, 1); }
        __syncthreads();
        if (tid == 0) { g_flag_ei = s_ei; g_flag_b = s_b; }
    }
}

// ---------------------------------------------------------------------------
// Kernel 2: dst histogram (decodes only dst half of raw edge_index)
// ---------------------------------------------------------------------------
__global__ void k_hist(const void* __restrict__ ei_raw)
{
    const int tid = blockIdx.x * 256 + threadIdx.x;
    const int is32 = g_flag_ei;
#pragma unroll
    for (int q = 0; q < 2; q++) {
        const int e = tid + q * (EBLK2 * 256);
        if (e < NE) atomicAdd(&g_cnt[edge_at(ei_raw, NE + e, is32)], 1);
    }
}

// ---------------------------------------------------------------------------
// Kernel 3: single-pass scan (block scan + atomic base; bases need not be
// monotone since consumers use beg + cnt) fused with graph-boundary build.
// ---------------------------------------------------------------------------
__global__ void k_scan_bounds(const void* __restrict__ b_raw)
{
    __shared__ int s[256];
    __shared__ int base_sh;
    const int tid = threadIdx.x;
    const int i = blockIdx.x * 256 + tid;
    const int v = (i < NN) ? g_cnt[i] : 0;
    s[tid] = v;
    __syncthreads();
#pragma unroll
    for (int d = 1; d < 256; d <<= 1) {
        const int t = (tid >= d) ? s[tid - d] : 0;
        __syncthreads();
        s[tid] += t;
        __syncthreads();
    }
    if (tid == 255) base_sh = atomicAdd(&g_total, s[255]);
    __syncthreads();
    if (i < NN) {
        const int o = base_sh + s[tid] - v;
        g_off[i] = o;
        g_cur[i] = o;
    }

    if (i < NN) {
        const int is32 = g_flag_b;
        const int g  = batch_at(b_raw, i, is32);
        const int gp = (i == 0) ? -1 : batch_at(b_raw, i - 1, is32);
        for (int q = gp + 1; q <= g; q++) g_gstart[q] = i;
        if (i == NN - 1)
            for (int q = g + 1; q <= NG; q++) g_gstart[q] = NN;
    }
}

// ---------------------------------------------------------------------------
// Kernel 4 (fused): blocks [0,GBLK) = GEMM1; blocks [GBLK,GBLK+EBLK2) = CSR
// scatter (decodes raw edges directly).
// GEMM1: [50000,200] @ [W1r|W1l][200,64], packed f32x2, double-buffered smem.
// 256 threads / 128 nodes / 64 cols; 4x8 micro-tile; warps 0-3 stage X,
// warps 4-7 stage W. ~70 regs -> 3 CTAs/SM (24 warps).
// ---------------------------------------------------------------------------
__global__ __launch_bounds__(256) void k_gemm1_scatter(const float* __restrict__ x,
                                                       const float* __restrict__ Wr,
                                                       const float* __restrict__ Wl,
                                                       const float* __restrict__ b,
                                                       const void* __restrict__ ei_raw)
{
    if (blockIdx.x >= GBLK) {
        const int base = (blockIdx.x - GBLK) * 512 + threadIdx.x;
        const int is32 = g_flag_ei;
#pragma unroll
        for (int q = 0; q < 2; q++) {
            const int e = base + q * 256;
            if (e < NE) {
                const int d = edge_at(ei_raw, NE + e, is32);
                const int s = edge_at(ei_raw, e, is32);
                const int pos = atomicAdd(&g_cur[d], 1);
                g_esrc[pos] = s;
            }
        }
        return;
    }

    __shared__ __align__(16) float Xs[2][8 * 128];   // [buf][k][node]
    __shared__ __align__(16) float Wsc[2][8 * 64];   // [buf][k*64+c]
    __shared__ float bs[32];

    const int tid = threadIdx.x;
    const int n0  = blockIdx.x * 128;
    if (tid < 32) bs[tid] = b[tid];

    const int cg = tid & 7;        // col group (8 cols = 4 packed pairs)
    const int ng = tid >> 3;       // node group (4 nodes), 0..31

    unsigned long long acc2[4][4];
#pragma unroll
    for (int i = 0; i < 4; i++)
#pragma unroll
        for (int j = 0; j < 4; j++) acc2[i][j] = 0ULL;

    const bool is_x_loader = tid < 128;
    const int  nld = n0 + tid;                       // X loader's node
    const bool vld = is_x_loader && (nld < NN);
    const float4* xrow = reinterpret_cast<const float4*>(x + (long)nld * DIN);
    const int widx = tid - 128;                      // W loader's lane (0..127)

    float4 xa, xb;
    float  wv[4];

#define LOAD_TILE(t)                                                          \
    do {                                                                      \
        if (is_x_loader) {                                                    \
            xa = make_float4(0.f, 0.f, 0.f, 0.f); xb = xa;                    \
            if (vld) { xa = xrow[(t) * 2]; xb = xrow[(t) * 2 + 1]; }          \
        } else {                                                              \
            _Pragma("unroll")                                                 \
            for (int j = 0; j < 4; j++) {                                     \
                const int idx = widx + j * 128;      /* 0..511 = kk*64+c */   \
                const int kk = idx >> 6, c = idx & 63;                        \
                wv[j] = (c < 32) ? Wr[((t) * 8 + kk) * 32 + c]                \
                                 : Wl[((t) * 8 + kk) * 32 + c - 32];          \
            }                                                                 \
        }                                                                     \
    } while (0)

#define STORE_TILE(bf)                                                        \
    do {                                                                      \
        if (is_x_loader) {                                                    \
            Xs[bf][0 * 128 + tid] = xa.x; Xs[bf][1 * 128 + tid] = xa.y;       \
            Xs[bf][2 * 128 + tid] = xa.z; Xs[bf][3 * 128 + tid] = xa.w;       \
            Xs[bf][4 * 128 + tid] = xb.x; Xs[bf][5 * 128 + tid] = xb.y;       \
            Xs[bf][6 * 128 + tid] = xb.z; Xs[bf][7 * 128 + tid] = xb.w;       \
        } else {                                                              \
            _Pragma("unroll")                                                 \
            for (int j = 0; j < 4; j++) Wsc[bf][widx + j * 128] = wv[j];      \
        }                                                                     \
    } while (0)

    LOAD_TILE(0);
    STORE_TILE(0);
    __syncthreads();

    int buf = 0;
    for (int t = 0; t < 25; t++) {
        if (t < 24) LOAD_TILE(t + 1);                // LDG in flight during compute

#pragma unroll
        for (int kk = 0; kk < 8; kk++) {
            const float4 a0 = *reinterpret_cast<const float4*>(Xs[buf] + kk * 128 + ng * 4);
            const unsigned long long* wp =
                reinterpret_cast<const unsigned long long*>(Wsc[buf] + kk * 64 + cg * 8);
            const unsigned long long w0 = wp[0], w1p = wp[1], w2p = wp[2], w3p = wp[3];
            const float xv[4] = {a0.x, a0.y, a0.z, a0.w};
#pragma unroll
            for (int i = 0; i < 4; i++) {
                unsigned long long xd;
                DUP_X2(xd, xv[i]);
                FMA_X2(acc2[i][0], xd, w0);
                FMA_X2(acc2[i][1], xd, w1p);
                FMA_X2(acc2[i][2], xd, w2p);
                FMA_X2(acc2[i][3], xd, w3p);
            }
        }

        if (t < 24) STORE_TILE(buf ^ 1);             // other buffer: race-free
        __syncthreads();
        buf ^= 1;
    }
#undef LOAD_TILE
#undef STORE_TILE

    const int c0 = cg * 8;
#pragma unroll
    for (int i = 0; i < 4; i++) {
        const int node = n0 + ng * 4 + i;
        if (node >= NN) continue;
        float c[8];
#pragma unroll
        for (int j = 0; j < 4; j++) UNPK_X2(c[2 * j], c[2 * j + 1], acc2[i][j]);
        float4 lo = make_float4(c[0], c[1], c[2], c[3]);
        float4 hi = make_float4(c[4], c[5], c[6], c[7]);
        if (cg < 4) {
            *reinterpret_cast<float4*>(g_tr_a + node * DH + c0)     = lo;
            *reinterpret_cast<float4*>(g_tr_a + node * DH + c0 + 4) = hi;
        } else {
            const int cc = c0 - 32;
            lo.x += bs[cc + 0]; lo.y += bs[cc + 1]; lo.z += bs[cc + 2]; lo.w += bs[cc + 3];
            hi.x += bs[cc + 4]; hi.y += bs[cc + 5]; hi.z += bs[cc + 6]; hi.w += bs[cc + 7];
            *reinterpret_cast<float4*>(g_root_a + node * DH + cc)     = lo;
            *reinterpret_cast<float4*>(g_root_a + node * DH + cc + 4) = hi;
        }
    }
}

// ---------------------------------------------------------------------------
// Fused layer kernel (layers 1->2, 2->3): warp per node; buffers picked by sel
// in device code (sel=0: a->b, sel=1: b->a).
// ---------------------------------------------------------------------------
__global__ __launch_bounds__(256) void k_flayer(int sel,
                                                const float* __restrict__ Wr,
                                                const float* __restrict__ Wl,
                                                const float* __restrict__ b)
{
    __shared__ __align__(16) unsigned long long Wp[32 * 32];  // [k][lane]=(Wr,Wl)
    __shared__ float bs[32];
    __shared__ float hs[8][32];

    const int tid = threadIdx.x;
    for (int i = tid; i < 1024; i += 256) {
        const int k = i >> 5, c = i & 31;
        unsigned long long p;
        PACK_X2(p, Wr[k * 32 + c], Wl[k * 32 + c]);
        Wp[i] = p;
    }
    if (tid < 32) bs[tid] = b[tid];
    __syncthreads();

    const float* tr_in   = sel ? g_tr_b   : g_tr_a;
    const float* root_in = sel ? g_root_b : g_root_a;
    float* tr_out   = sel ? g_tr_a   : g_tr_b;
    float* root_out = sel ? g_root_a : g_root_b;

    const int w    = tid >> 5;
    const int lane = tid & 31;
    const int node = (blockIdx.x << 3) + w;
    if (node >= NN) return;

    const int beg = g_off[node];
    const int end = beg + g_cnt[node];
    float acc = 0.f;
    int k = beg;
    for (; k + 3 < end; k += 4) {
        const int s0 = g_esrc[k + 0], s1 = g_esrc[k + 1];
        const int s2 = g_esrc[k + 2], s3 = g_esrc[k + 3];
        acc += tr_in[s0 * DH + lane] + tr_in[s1 * DH + lane]
             + tr_in[s2 * DH + lane] + tr_in[s3 * DH + lane];
    }
    for (; k < end; k++) acc += tr_in[g_esrc[k] * DH + lane];

    const float h = elu1(acc + root_in[node * DH + lane]);
    hs[w][lane] = h;
    __syncwarp();

    unsigned long long a2 = 0ULL;
#pragma unroll
    for (int kk = 0; kk < 32; kk++) {
        unsigned long long hd;
        DUP_X2(hd, hs[w][kk]);                    // LDS broadcast
        FMA_X2(a2, hd, Wp[kk * 32 + lane]);
    }
    float m, r;
    UNPK_X2(m, r, a2);
    tr_out[node * DH + lane]   = m;
    root_out[node * DH + lane] = r + bs[lane];
}

// ---------------------------------------------------------------------------
// Fused layer 3 + pool: reads a-buffers; h = elu(aggr + root); atomic pool.
// ---------------------------------------------------------------------------
__global__ __launch_bounds__(256) void k_flayer3_pool(const void* __restrict__ b_raw)
{
    const int tid  = threadIdx.x;
    const int w    = tid >> 5;
    const int lane = tid & 31;
    const int node = (blockIdx.x << 3) + w;
    if (node >= NN) return;

    const int beg = g_off[node];
    const int end = beg + g_cnt[node];
    float acc = 0.f;
    int k = beg;
    for (; k + 3 < end; k += 4) {
        const int s0 = g_esrc[k + 0], s1 = g_esrc[k + 1];
        const int s2 = g_esrc[k + 2], s3 = g_esrc[k + 3];
        acc += g_tr_a[s0 * DH + lane] + g_tr_a[s1 * DH + lane]
             + g_tr_a[s2 * DH + lane] + g_tr_a[s3 * DH + lane];
    }
    for (; k < end; k++) acc += g_tr_a[g_esrc[k] * DH + lane];

    const float h = elu1(acc + g_root_a[node * DH + lane]);
    const int g = batch_at(b_raw, node, g_flag_b);
    atomicAdd(&g_sums[g * DH + lane], h);
}

// ---------------------------------------------------------------------------
// Head: pooled mean -> linear[32,2] -> log_softmax
// ---------------------------------------------------------------------------
__global__ void k_head(const float* __restrict__ Wlin, const float* __restrict__ blin,
                       float* __restrict__ out)
{
    const int gph = threadIdx.x;
    if (gph >= NG) return;
    const int cnt = g_gstart[gph + 1] - g_gstart[gph];
    const float inv = 1.f / fmaxf((float)cnt, 1.f);
    float l0 = blin[0], l1 = blin[1];
#pragma unroll
    for (int c = 0; c < DH; c++) {
        const float p = g_sums[gph * DH + c] * inv;
        l0 += p * Wlin[c * 2 + 0];
        l1 += p * Wlin[c * 2 + 1];
    }
    const float m   = fmaxf(l0, l1);
    const float lse = m + logf(expf(l0 - m) + expf(l1 - m));
    out[gph * 2 + 0] = l0 - lse;
    out[gph * 2 + 1] = l1 - lse;
}

// ---------------------------------------------------------------------------
extern "C" void kernel_launch(void* const* d_in, const int* in_sizes, int n_in,
                              void* d_out, int out_size)
{
    const void *p_x = 0, *p_ei = 0, *p_batch = 0;
    const void *p_W1[2] = {0, 0};
    const void *p_W23[4] = {0, 0, 0, 0};
    const void *p_b[3] = {0, 0, 0};
    const void *p_Wlin = 0, *p_blin = 0;
    int n64 = 0, n1024 = 0, n32 = 0;
    for (int i = 0; i < n_in; i++) {
        const int s = in_sizes[i];
        if      (s == NN * DIN) p_x = d_in[i];
        else if (s == 2 * NE)   p_ei = d_in[i];
        else if (s == NN)       p_batch = d_in[i];
        else if (s == DIN * DH) { if (n64 < 2) p_W1[n64++] = d_in[i]; }
        else if (s == DH * DH)  { if (n1024 < 4) p_W23[n1024++] = d_in[i]; }
        else if (s == DH)       { if (n32 < 3) p_b[n32++] = d_in[i]; }
        else if (s == DH * 2)   p_Wlin = d_in[i];
        else if (s == 2)        p_blin = d_in[i];
    }
    const float* x    = (const float*)p_x;
    const float* W1r  = (const float*)p_W1[0];
    const float* W1l  = (const float*)p_W1[1];
    const float* b1   = (const float*)p_b[0];
    const float* W2r  = (const float*)p_W23[0];
    const float* W2l  = (const float*)p_W23[1];
    const float* b2   = (const float*)p_b[1];
    const float* W3r  = (const float*)p_W23[2];
    const float* W3l  = (const float*)p_W23[3];
    const float* b3   = (const float*)p_b[2];
    const float* Wlin = (const float*)p_Wlin;
    const float* blin = (const float*)p_blin;
    float* out = (float*)d_out;

    const int FBLKS = (NN + 7) / 8;               // 6250 (warp per node)

    k_detect_zero<<<NBLK, 256>>>((const unsigned*)p_ei, (const unsigned*)p_batch);
    k_hist<<<EBLK2, 256>>>(p_ei);
    k_scan_bounds<<<NBLK, 256>>>(p_batch);
    k_gemm1_scatter<<<GBLK + EBLK2, 256>>>(x, W1r, W1l, b1, p_ei);
    k_flayer<<<FBLKS, 256>>>(0, W2r, W2l, b2);    // a -> b (layer 1 act + layer 2 linear)
    k_flayer<<<FBLKS, 256>>>(1, W3r, W3l, b3);    // b -> a (layer 2 act + layer 3 linear)
    k_flayer3_pool<<<FBLKS, 256>>>(p_batch);      // layer 3 act + pool
    k_head<<<1, 64>>>(Wlin, blin, out);
}